// round 3
// baseline (speedup 1.0000x reference)
#include <cuda_runtime.h>

// Problem constants
#define BB 2
#define LL 2048
#define DD 1024
#define HH 16
#define DHD 64

// Scratch for projected Q,K,V in [B, H, L, Dh] layout. 3 x 16 MiB.
__device__ float g_P[3][(size_t)BB * HH * LL * DHD];

// ---------------------------------------------------------------------------
// Projection GEMM: out[b][h][l][d] = sum_k X[b*L+l][k] * W[k][h*64+d] * scale
// Tile: 64(M) x 64(N) x 16(K), 256 threads, 4x4 register micro-tile.
// Each N-tile (blockIdx.x) is exactly one head (64 cols), so output maps
// directly into head-separated layout.
// Early-exit row tiles whose sequence positions are fully masked (never read).
// ---------------------------------------------------------------------------
__global__ __launch_bounds__(256) void proj_kernel(
    const float* __restrict__ X, const float* __restrict__ W,
    const int* __restrict__ lenp, int which, float scale)
{
    float* __restrict__ out = g_P[which];
    const int bn   = blockIdx.x;        // head index / col tile, 0..15
    const int bm   = blockIdx.y;        // row tile, 0..63
    const int row0 = bm * 64;
    const int b    = row0 / LL;
    const int l0   = row0 % LL;
    if (l0 >= lenp[b]) return;          // masked rows are never consumed

    __shared__ float As[16][68];        // A tile, k-major (transposed)
    __shared__ float Bs[16][68];        // B tile, natural

    const int tid = threadIdx.x;
    const int tx  = tid & 15;           // output col group
    const int ty  = tid >> 4;           // output row group

    float acc[4][4];
#pragma unroll
    for (int i = 0; i < 4; i++)
#pragma unroll
        for (int j = 0; j < 4; j++) acc[i][j] = 0.f;

    const int ar = tid >> 2;            // A row within tile, 0..63
    const int ac = (tid & 3) * 4;       // A col offset (float4), 0..12
    const int br = tid >> 4;            // B row within tile, 0..15
    const int bc = (tid & 15) * 4;      // B col offset (float4)

    const float* Xp = X + (size_t)row0 * DD;
    const float* Wp = W + bn * 64;

    for (int k0 = 0; k0 < DD; k0 += 16) {
        float4 av = *(const float4*)(Xp + (size_t)ar * DD + k0 + ac);
        As[ac + 0][ar] = av.x;
        As[ac + 1][ar] = av.y;
        As[ac + 2][ar] = av.z;
        As[ac + 3][ar] = av.w;
        float4 bv = *(const float4*)(Wp + (size_t)(k0 + br) * DD + bc);
        *(float4*)&Bs[br][bc] = bv;
        __syncthreads();
#pragma unroll
        for (int k = 0; k < 16; k++) {
            float4 a4 = *(const float4*)&As[k][ty * 4];
            float4 b4 = *(const float4*)&Bs[k][tx * 4];
            float a[4] = {a4.x, a4.y, a4.z, a4.w};
            float bb[4] = {b4.x, b4.y, b4.z, b4.w};
#pragma unroll
            for (int i = 0; i < 4; i++)
#pragma unroll
                for (int j = 0; j < 4; j++) acc[i][j] += a[i] * bb[j];
        }
        __syncthreads();
    }

    // out[((b*H + bn)*L + l) * 64 + d]
    float* op = out + ((size_t)(b * HH + bn) * LL + l0) * DHD;
#pragma unroll
    for (int i = 0; i < 4; i++) {
        int r = ty * 4 + i;
        float4 v = make_float4(acc[i][0] * scale, acc[i][1] * scale,
                               acc[i][2] * scale, acc[i][3] * scale);
        *(float4*)(op + (size_t)r * DHD + tx * 4) = v;
    }
}

// ---------------------------------------------------------------------------
// Flash attention per (b, h, q-tile of 64 rows). 256 threads, 4x4 micro-tiles.
// KV loop bounded at ceil(v_len/64): masked keys contribute exp(-1e12-..) = 0
// exactly in fp32, so skipping them is bit-equivalent to the reference.
// Rows >= q_len are written as zeros (multiplicative query mask).
// smem rows padded to stride 68 floats (16B-aligned, conflict-reduced).
// ---------------------------------------------------------------------------
#define SMS 68
#define ATTN_SMEM (4 * 64 * SMS * (int)sizeof(float))

__global__ __launch_bounds__(256) void attn_kernel(
    const int* __restrict__ q_lenp, const int* __restrict__ v_lenp,
    float* __restrict__ out)
{
    const int qt  = blockIdx.x;         // 0..31
    const int h   = blockIdx.y;         // 0..15
    const int b   = blockIdx.z;         // 0..1
    const int tid = threadIdx.x;
    const int tx  = tid & 15;
    const int ty  = tid >> 4;
    const int l0  = qt * 64;
    const int q_len = q_lenp[b];
    const int v_len = v_lenp[b];

    float* outp = out + (size_t)b * LL * DD + h * DHD;

    if (l0 >= q_len) {                  // whole tile masked -> zeros
#pragma unroll
        for (int i = 0; i < 4; i++) {
            int r = l0 + ty * 4 + i;
            *(float4*)(outp + (size_t)r * DD + tx * 4) = make_float4(0.f, 0.f, 0.f, 0.f);
        }
        return;
    }

    extern __shared__ float sm[];
    float* Qt = sm;                     // [d][row]  (d-major)
    float* Kt = sm + 64 * SMS;          // [d][kcol] (d-major)
    float* Vs = sm + 2 * 64 * SMS;      // [krow][d] (natural)
    float* Pt = sm + 3 * 64 * SMS;      // [kcol][qrow]

    const float* Qp = g_P[0] + ((size_t)(b * HH + h) * LL + l0) * DHD;
    const float* Kp = g_P[1] + (size_t)(b * HH + h) * LL * DHD;
    const float* Vp = g_P[2] + (size_t)(b * HH + h) * LL * DHD;

    // Load Q tile once, transposed to d-major
    {
        const int r  = tid >> 2;        // 0..63
        const int c0 = (tid & 3) * 16;  // 0,16,32,48
#pragma unroll
        for (int u = 0; u < 4; u++) {
            float4 v = *(const float4*)(Qp + (size_t)r * DHD + c0 + u * 4);
            Qt[(c0 + u * 4 + 0) * SMS + r] = v.x;
            Qt[(c0 + u * 4 + 1) * SMS + r] = v.y;
            Qt[(c0 + u * 4 + 2) * SMS + r] = v.z;
            Qt[(c0 + u * 4 + 3) * SMS + r] = v.w;
        }
    }

    float acc[4][4];
    float m_i[4], l_i[4];
#pragma unroll
    for (int i = 0; i < 4; i++) {
        m_i[i] = -1e30f;
        l_i[i] = 0.f;
#pragma unroll
        for (int j = 0; j < 4; j++) acc[i][j] = 0.f;
    }

    const int nkt = (v_len + 63) >> 6;
    for (int kt = 0; kt < nkt; kt++) {
        const int k0 = kt * 64;
        // Load K (transposed, d-major) and V (natural)
        {
            const int r  = tid >> 2;
            const int c0 = (tid & 3) * 16;
#pragma unroll
            for (int u = 0; u < 4; u++) {
                float4 kv = *(const float4*)(Kp + (size_t)(k0 + r) * DHD + c0 + u * 4);
                Kt[(c0 + u * 4 + 0) * SMS + r] = kv.x;
                Kt[(c0 + u * 4 + 1) * SMS + r] = kv.y;
                Kt[(c0 + u * 4 + 2) * SMS + r] = kv.z;
                Kt[(c0 + u * 4 + 3) * SMS + r] = kv.w;
                float4 vv = *(const float4*)(Vp + (size_t)(k0 + r) * DHD + c0 + u * 4);
                *(float4*)&Vs[r * SMS + c0 + u * 4] = vv;
            }
        }
        __syncthreads();

        // S = (Q * scale) @ K^T   (scale folded into Q at projection time)
        float s[4][4];
#pragma unroll
        for (int i = 0; i < 4; i++)
#pragma unroll
            for (int j = 0; j < 4; j++) s[i][j] = 0.f;
#pragma unroll 8
        for (int d = 0; d < 64; d++) {
            float4 a4 = *(const float4*)&Qt[d * SMS + ty * 4];
            float4 b4 = *(const float4*)&Kt[d * SMS + tx * 4];
            float a[4] = {a4.x, a4.y, a4.z, a4.w};
            float bb[4] = {b4.x, b4.y, b4.z, b4.w};
#pragma unroll
            for (int i = 0; i < 4; i++)
#pragma unroll
                for (int j = 0; j < 4; j++) s[i][j] += a[i] * bb[j];
        }

        // key mask on the tail tile
#pragma unroll
        for (int jj = 0; jj < 4; jj++) {
            if (k0 + tx * 4 + jj >= v_len) {
#pragma unroll
                for (int ii = 0; ii < 4; ii++) s[ii][jj] = -1e30f;
            }
        }

        // online softmax (row stats across the 16 tx lanes)
#pragma unroll
        for (int ii = 0; ii < 4; ii++) {
            float mt = fmaxf(fmaxf(s[ii][0], s[ii][1]), fmaxf(s[ii][2], s[ii][3]));
#pragma unroll
            for (int off = 1; off < 16; off <<= 1)
                mt = fmaxf(mt, __shfl_xor_sync(0xffffffffu, mt, off));
            float mn = fmaxf(m_i[ii], mt);
            float alpha = __expf(m_i[ii] - mn);
            float rs = 0.f;
#pragma unroll
            for (int jj = 0; jj < 4; jj++) {
                float p = __expf(s[ii][jj] - mn);
                s[ii][jj] = p;
                rs += p;
            }
#pragma unroll
            for (int off = 1; off < 16; off <<= 1)
                rs += __shfl_xor_sync(0xffffffffu, rs, off);
            l_i[ii] = l_i[ii] * alpha + rs;
            m_i[ii] = mn;
#pragma unroll
            for (int jj = 0; jj < 4; jj++) acc[ii][jj] *= alpha;
            // stage P transposed: Pt[kcol][qrow]
#pragma unroll
            for (int jj = 0; jj < 4; jj++)
                Pt[(tx * 4 + jj) * SMS + ty * 4 + ii] = s[ii][jj];
        }
        __syncthreads();

        // O += P @ V
#pragma unroll 8
        for (int j = 0; j < 64; j++) {
            float4 a4 = *(const float4*)&Pt[j * SMS + ty * 4];
            float4 b4 = *(const float4*)&Vs[j * SMS + tx * 4];
            float a[4] = {a4.x, a4.y, a4.z, a4.w};
            float bb[4] = {b4.x, b4.y, b4.z, b4.w};
#pragma unroll
            for (int i = 0; i < 4; i++)
#pragma unroll
                for (int jj = 0; jj < 4; jj++) acc[i][jj] += a[i] * bb[jj];
        }
        __syncthreads();
    }

    // finalize + query mask
#pragma unroll
    for (int ii = 0; ii < 4; ii++) {
        int r = l0 + ty * 4 + ii;
        float inv = 1.f / l_i[ii];
        float4 o;
        if (r < q_len) {
            o = make_float4(acc[ii][0] * inv, acc[ii][1] * inv,
                            acc[ii][2] * inv, acc[ii][3] * inv);
        } else {
            o = make_float4(0.f, 0.f, 0.f, 0.f);
        }
        *(float4*)(outp + (size_t)r * DD + tx * 4) = o;
    }
}

// ---------------------------------------------------------------------------
extern "C" void kernel_launch(void* const* d_in, const int* in_sizes, int n_in,
                              void* d_out, int out_size)
{
    (void)in_sizes; (void)n_in; (void)out_size;
    const float* Q_seq = (const float*)d_in[0];
    const float* K_seq = (const float*)d_in[1];
    const float* V_seq = (const float*)d_in[2];
    const int*   q_len = (const int*)d_in[3];
    const int*   v_len = (const int*)d_in[4];
    const float* WQ    = (const float*)d_in[5];
    const float* WK    = (const float*)d_in[6];
    const float* WV    = (const float*)d_in[7];
    float* out = (float*)d_out;

    // Projections: grid = (N tiles = 16 heads, M tiles = 64)
    dim3 pgrid(DD / 64, (BB * LL) / 64);
    const float qscale = 0.125f;  // 1/sqrt(64)
    proj_kernel<<<pgrid, 256>>>(Q_seq, WQ, q_len, 0, qscale);
    proj_kernel<<<pgrid, 256>>>(K_seq, WK, v_len, 1, 1.0f);
    proj_kernel<<<pgrid, 256>>>(V_seq, WV, v_len, 2, 1.0f);

    // Attention: grid = (32 q-tiles, 16 heads, 2 batches)
    cudaFuncSetAttribute(attn_kernel, cudaFuncAttributeMaxDynamicSharedMemorySize,
                         ATTN_SMEM);
    attn_kernel<<<dim3(LL / 64, HH, BB), 256, ATTN_SMEM>>>(q_len, v_len, out);
}

// round 7
// speedup vs baseline: 1.0587x; 1.0587x over previous
#include <cuda_runtime.h>

#define BB 2
#define LL 2048
#define DD 1024
#define HH 16
#define DHD 64

// Scratch: projected Q,K,V in [B, H, L, Dh] layout.
__device__ float g_P[3][(size_t)BB * HH * LL * DHD];

// ---------------------------------------------------------------------------
// Fused projection GEMMs (z = 0:Q, 1:K, 2:V). Scalar FFMA.
// Tile 128(M) x 64(N = one head), K-chunk 32, 128 threads, 8x8 micro.
// ---------------------------------------------------------------------------
__global__ __launch_bounds__(128) void proj_kernel(
    const float* __restrict__ Xq, const float* __restrict__ Xk,
    const float* __restrict__ Xv,
    const float* __restrict__ Wq, const float* __restrict__ Wk,
    const float* __restrict__ Wv,
    const int* __restrict__ q_lenp, const int* __restrict__ v_lenp)
{
    const int which = blockIdx.z;
    const float* X = (which == 0) ? Xq : (which == 1) ? Xk : Xv;
    const float* W = (which == 0) ? Wq : (which == 1) ? Wk : Wv;
    const int*  lenp = (which == 0) ? q_lenp : v_lenp;
    const float scale = (which == 0) ? 0.125f : 1.0f;

    const int bn   = blockIdx.x;         // head, 0..15
    const int bm   = blockIdx.y;         // row tile, 0..31
    const int row0 = bm * 128;
    const int b    = row0 / LL;
    const int l0   = row0 % LL;
    if (l0 >= lenp[b]) return;

    __shared__ __align__(16) float As[32][136];  // k-major (transposed X tile)
    __shared__ __align__(16) float Bs[32][72];   // natural W tile

    const int tid = threadIdx.x;
    const int tx  = tid & 7;             // col group (8 cols)
    const int ty  = tid >> 3;            // row group (8 rows)

    float acc[8][8];
#pragma unroll
    for (int i = 0; i < 8; i++)
#pragma unroll
        for (int j = 0; j < 8; j++) acc[i][j] = 0.f;

    const float* Xp = X + (size_t)row0 * DD;
    const float* Wp = W + bn * 64;
    const int wr = tid >> 2;             // W row 0..31
    const int wc = (tid & 3) * 16;       // W col base

    for (int k0 = 0; k0 < DD; k0 += 32) {
        // X tile: one row per thread, transpose-scatter
#pragma unroll
        for (int u = 0; u < 8; u++) {
            float4 v = *(const float4*)(Xp + (size_t)tid * DD + k0 + u * 4);
            As[u * 4 + 0][tid] = v.x;
            As[u * 4 + 1][tid] = v.y;
            As[u * 4 + 2][tid] = v.z;
            As[u * 4 + 3][tid] = v.w;
        }
        // W tile: natural
#pragma unroll
        for (int u = 0; u < 4; u++) {
            float4 v = *(const float4*)(Wp + (size_t)(k0 + wr) * DD + wc + u * 4);
            *(float4*)&Bs[wr][wc + u * 4] = v;
        }
        __syncthreads();
#pragma unroll 8
        for (int k = 0; k < 32; k++) {
            float4 a0 = *(const float4*)&As[k][ty * 8];
            float4 a1 = *(const float4*)&As[k][ty * 8 + 4];
            float4 b0 = *(const float4*)&Bs[k][tx * 8];
            float4 b1 = *(const float4*)&Bs[k][tx * 8 + 4];
            float a[8] = {a0.x, a0.y, a0.z, a0.w, a1.x, a1.y, a1.z, a1.w};
            float bb[8] = {b0.x, b0.y, b0.z, b0.w, b1.x, b1.y, b1.z, b1.w};
#pragma unroll
            for (int i = 0; i < 8; i++)
#pragma unroll
                for (int j = 0; j < 8; j++) acc[i][j] += a[i] * bb[j];
        }
        __syncthreads();
    }

    float* op = g_P[which] + ((size_t)(b * HH + bn) * LL + l0) * DHD;
#pragma unroll
    for (int i = 0; i < 8; i++) {
        int r = ty * 8 + i;
        float4 v0 = make_float4(acc[i][0] * scale, acc[i][1] * scale,
                                acc[i][2] * scale, acc[i][3] * scale);
        float4 v1 = make_float4(acc[i][4] * scale, acc[i][5] * scale,
                                acc[i][6] * scale, acc[i][7] * scale);
        *(float4*)(op + (size_t)r * DHD + tx * 8)     = v0;
        *(float4*)(op + (size_t)r * DHD + tx * 8 + 4) = v1;
    }
}

// ---------------------------------------------------------------------------
// Flash attention: tile 128(q) x 128(k), 256 threads, scalar FFMA.
// S micro-tile 8x8 (tx covers 128 k-cols), O micro-tile 8x4 (tx covers 64 d).
// Layouts (floats):
//   Qt [64 d][QKS=136]  d-major     Kt [64 d][QKS=136] d-major
//   Vs [128 k][VPS=68]  natural     Pt [128 q][PTS=132] natural [q][k]
// ---------------------------------------------------------------------------
#define QKS 136
#define VPS 68
#define PTS 132
#define ATTN_SMEM ((2 * 64 * QKS + 128 * VPS + 128 * PTS) * (int)sizeof(float))

__global__ __launch_bounds__(256, 1) void attn_kernel(
    const int* __restrict__ q_lenp, const int* __restrict__ v_lenp,
    float* __restrict__ out)
{
    const int qt  = blockIdx.x;          // 0..15
    const int h   = blockIdx.y;
    const int b   = blockIdx.z;
    const int tid = threadIdx.x;
    const int tx  = tid & 15;
    const int ty  = tid >> 4;
    const int l0  = qt * 128;
    const int q_len = q_lenp[b];
    const int v_len = v_lenp[b];

    float* outp = out + (size_t)b * LL * DD + h * DHD;
    const int lr = tid >> 1;             // loader row 0..127
    const int lc = (tid & 1) * 32;       // loader col base

    if (l0 >= q_len) {                   // fully masked q tile
#pragma unroll
        for (int u = 0; u < 8; u++)
            *(float4*)(outp + (size_t)(l0 + lr) * DD + lc + u * 4) =
                make_float4(0.f, 0.f, 0.f, 0.f);
        return;
    }

    extern __shared__ __align__(16) float sm[];
    float* Qt = sm;
    float* Kt = sm + 64 * QKS;
    float* Vs = sm + 2 * 64 * QKS;
    float* Pt = Vs + 128 * VPS;

    const float* Qp = g_P[0] + ((size_t)(b * HH + h) * LL + l0) * DHD;
    const float* Kp = g_P[1] + (size_t)(b * HH + h) * LL * DHD;
    const float* Vp = g_P[2] + (size_t)(b * HH + h) * LL * DHD;

    // Load Q tile transposed (d-major)
#pragma unroll
    for (int u = 0; u < 8; u++) {
        float4 v = *(const float4*)(Qp + (size_t)lr * DHD + lc + u * 4);
        Qt[(lc + u * 4 + 0) * QKS + lr] = v.x;
        Qt[(lc + u * 4 + 1) * QKS + lr] = v.y;
        Qt[(lc + u * 4 + 2) * QKS + lr] = v.z;
        Qt[(lc + u * 4 + 3) * QKS + lr] = v.w;
    }

    float acc[8][4];                     // O accumulators, d-cols tx*4..+3
    float m_i[8], l_i[8];
#pragma unroll
    for (int i = 0; i < 8; i++) {
        m_i[i] = -1e30f; l_i[i] = 0.f;
#pragma unroll
        for (int j = 0; j < 4; j++) acc[i][j] = 0.f;
    }

    const int nkt = (v_len + 127) >> 7;
    for (int kt = 0; kt < nkt; kt++) {
        const int k0 = kt * 128;
        // K transposed (d-major), V natural
#pragma unroll
        for (int u = 0; u < 8; u++) {
            float4 kv = *(const float4*)(Kp + (size_t)(k0 + lr) * DHD + lc + u * 4);
            Kt[(lc + u * 4 + 0) * QKS + lr] = kv.x;
            Kt[(lc + u * 4 + 1) * QKS + lr] = kv.y;
            Kt[(lc + u * 4 + 2) * QKS + lr] = kv.z;
            Kt[(lc + u * 4 + 3) * QKS + lr] = kv.w;
            float4 vv = *(const float4*)(Vp + (size_t)(k0 + lr) * DHD + lc + u * 4);
            *(float4*)&Vs[lr * VPS + lc + u * 4] = vv;
        }
        __syncthreads();

        // S = Q @ K^T  (scale folded into Q); k-cols tx*8..+7
        float s[8][8];
#pragma unroll
        for (int i = 0; i < 8; i++)
#pragma unroll
            for (int j = 0; j < 8; j++) s[i][j] = 0.f;
#pragma unroll 4
        for (int d = 0; d < 64; d++) {
            float4 a0 = *(const float4*)&Qt[d * QKS + ty * 8];
            float4 a1 = *(const float4*)&Qt[d * QKS + ty * 8 + 4];
            float4 b0 = *(const float4*)&Kt[d * QKS + tx * 8];
            float4 b1 = *(const float4*)&Kt[d * QKS + tx * 8 + 4];
            float a[8] = {a0.x, a0.y, a0.z, a0.w, a1.x, a1.y, a1.z, a1.w};
            float bb[8] = {b0.x, b0.y, b0.z, b0.w, b1.x, b1.y, b1.z, b1.w};
#pragma unroll
            for (int i = 0; i < 8; i++)
#pragma unroll
                for (int j = 0; j < 8; j++) s[i][j] += a[i] * bb[j];
        }

        // tail-mask, online softmax, stage P
#pragma unroll
        for (int i = 0; i < 8; i++) {
#pragma unroll
            for (int jj = 0; jj < 8; jj++)
                if (k0 + tx * 8 + jj >= v_len) s[i][jj] = -1e30f;

            float mt = s[i][0];
#pragma unroll
            for (int jj = 1; jj < 8; jj++) mt = fmaxf(mt, s[i][jj]);
#pragma unroll
            for (int off = 1; off < 16; off <<= 1)
                mt = fmaxf(mt, __shfl_xor_sync(0xffffffffu, mt, off));
            float mn = fmaxf(m_i[i], mt);
            float alpha = __expf(m_i[i] - mn);
            float rs = 0.f;
#pragma unroll
            for (int jj = 0; jj < 8; jj++) {
                s[i][jj] = __expf(s[i][jj] - mn);
                rs += s[i][jj];
            }
#pragma unroll
            for (int off = 1; off < 16; off <<= 1)
                rs += __shfl_xor_sync(0xffffffffu, rs, off);
            l_i[i] = l_i[i] * alpha + rs;
            m_i[i] = mn;
#pragma unroll
            for (int j = 0; j < 4; j++) acc[i][j] *= alpha;
            *(float4*)&Pt[(ty * 8 + i) * PTS + tx * 8] =
                make_float4(s[i][0], s[i][1], s[i][2], s[i][3]);
            *(float4*)&Pt[(ty * 8 + i) * PTS + tx * 8 + 4] =
                make_float4(s[i][4], s[i][5], s[i][6], s[i][7]);
        }
        __syncthreads();

        // O += P @ V  (P reads warp-broadcast; d-cols tx*4..+3)
#pragma unroll 2
        for (int j = 0; j < 128; j++) {
            float4 b0 = *(const float4*)&Vs[j * VPS + tx * 4];
            float bb[4] = {b0.x, b0.y, b0.z, b0.w};
            float a[8];
#pragma unroll
            for (int i = 0; i < 8; i++) a[i] = Pt[(ty * 8 + i) * PTS + j];
#pragma unroll
            for (int i = 0; i < 8; i++)
#pragma unroll
                for (int jc = 0; jc < 4; jc++) acc[i][jc] += a[i] * bb[jc];
        }
        __syncthreads();
    }

    // finalize + query mask
#pragma unroll
    for (int i = 0; i < 8; i++) {
        int r = l0 + ty * 8 + i;
        float4 o;
        if (r < q_len) {
            float inv = 1.f / l_i[i];
            o = make_float4(acc[i][0] * inv, acc[i][1] * inv,
                            acc[i][2] * inv, acc[i][3] * inv);
        } else {
            o = make_float4(0.f, 0.f, 0.f, 0.f);
        }
        *(float4*)(outp + (size_t)r * DD + tx * 4) = o;
    }
}

// ---------------------------------------------------------------------------
extern "C" void kernel_launch(void* const* d_in, const int* in_sizes, int n_in,
                              void* d_out, int out_size)
{
    (void)in_sizes; (void)n_in; (void)out_size;
    const float* Q_seq = (const float*)d_in[0];
    const float* K_seq = (const float*)d_in[1];
    const float* V_seq = (const float*)d_in[2];
    const int*   q_len = (const int*)d_in[3];
    const int*   v_len = (const int*)d_in[4];
    const float* WQ    = (const float*)d_in[5];
    const float* WK    = (const float*)d_in[6];
    const float* WV    = (const float*)d_in[7];
    float* out = (float*)d_out;

    proj_kernel<<<dim3(HH, (BB * LL) / 128, 3), 128>>>(
        Q_seq, K_seq, V_seq, WQ, WK, WV, q_len, v_len);

    cudaFuncSetAttribute(attn_kernel, cudaFuncAttributeMaxDynamicSharedMemorySize,
                         ATTN_SMEM);
    attn_kernel<<<dim3(LL / 128, HH, BB), 256, ATTN_SMEM>>>(q_len, v_len, out);
}

// round 9
// speedup vs baseline: 1.2327x; 1.1644x over previous
#include <cuda_runtime.h>
#include <cstdint>

#define BB 2
#define LL 2048
#define DD 1024
#define HH 16
#define DHD 64

// Scratch: projected Q,K,V in [B, H, L, Dh] layout.
__device__ float g_P[3][(size_t)BB * HH * LL * DHD];

// ---------------------------------------------------------------------------
// tf32 helpers (mma.sync path, plain compute_103 — no 'a' features)
// ---------------------------------------------------------------------------
__device__ __forceinline__ uint32_t f2tf32(float x) {
    uint32_t r;
    asm("cvt.rna.tf32.f32 %0, %1;" : "=r"(r) : "f"(x));
    return r;
}
__device__ __forceinline__ void mma_tf32(float& c0, float& c1, float& c2, float& c3,
                                         uint32_t a0, uint32_t a1, uint32_t a2, uint32_t a3,
                                         uint32_t b0, uint32_t b1) {
    asm volatile(
        "mma.sync.aligned.m16n8k8.row.col.f32.tf32.tf32.f32 "
        "{%0,%1,%2,%3}, {%4,%5,%6,%7}, {%8,%9}, {%0,%1,%2,%3};"
        : "+f"(c0), "+f"(c1), "+f"(c2), "+f"(c3)
        : "r"(a0), "r"(a1), "r"(a2), "r"(a3), "r"(b0), "r"(b1));
}

// ---------------------------------------------------------------------------
// Projection GEMM via mma.sync tf32 with 3xTF32 split (fp32-grade accuracy).
// Block: 128(M) x 64(N = one head), 256 threads = 8 warps (4x2 warp grid).
// Warp tile 32x32; K staged in chunks of 32.
// Smem strides: A=36 (bank = 4g+t, conflict-free), B=68 (bank = 4t+g).
// out[b][h][l][d] = sum_k X[row][k] * W[k][h*64+d] * scale
// ---------------------------------------------------------------------------
#define ASTR 36
#define BSTR 68
#define PROJ_SMEM ((2 * 128 * ASTR + 2 * 32 * BSTR) * (int)sizeof(float))

__global__ __launch_bounds__(256) void proj_mma_kernel(
    const float* __restrict__ Xq, const float* __restrict__ Xk,
    const float* __restrict__ Xv,
    const float* __restrict__ Wq, const float* __restrict__ Wk,
    const float* __restrict__ Wv,
    const int* __restrict__ q_lenp, const int* __restrict__ v_lenp)
{
    const int which = blockIdx.z;
    const float* X = (which == 0) ? Xq : (which == 1) ? Xk : Xv;
    const float* W = (which == 0) ? Wq : (which == 1) ? Wk : Wv;
    const int* lenp = (which == 0) ? q_lenp : v_lenp;
    const float scale = (which == 0) ? 0.125f : 1.0f;

    const int head = blockIdx.x;          // 0..15
    const int bm   = blockIdx.y;          // 0..31
    const int row0 = bm * 128;
    const int n0   = head * 64;
    const int b    = row0 / LL;
    const int l0   = row0 % LL;
    if (l0 >= lenp[b]) return;

    extern __shared__ __align__(16) float psm[];
    float* Ah = psm;                       // [128][ASTR] tf32-hi
    float* Al = Ah + 128 * ASTR;           // [128][ASTR] tf32-lo
    float* Bh = Al + 128 * ASTR;           // [32][BSTR]
    float* Bl = Bh + 32 * BSTR;            // [32][BSTR]

    const int tid  = threadIdx.x;
    const int wid  = tid >> 5;
    const int lane = tid & 31;
    const int g    = lane >> 2;            // groupID
    const int t    = lane & 3;             // thread-in-group
    const int wm   = wid >> 1;             // 0..3 -> rows wm*32
    const int wn   = wid & 1;              // 0..1 -> cols wn*32

    float c[2][4][4];                      // [mf][nf][c0..c3]
#pragma unroll
    for (int i = 0; i < 2; i++)
#pragma unroll
        for (int j = 0; j < 4; j++)
#pragma unroll
            for (int q = 0; q < 4; q++) c[i][j][q] = 0.f;

    // Loader indices
    const int arow = tid >> 1;             // 0..127
    const int acol = (tid & 1) * 16;       // 0 / 16
    const int bn   = tid & 63;             // 0..63
    const int bk0  = tid >> 6;             // 0..3

    for (int k0 = 0; k0 < DD; k0 += 32) {
        // A tile: 128 x 32, split into hi/lo
        const float* xr = X + (size_t)(row0 + arow) * DD + k0 + acol;
#pragma unroll
        for (int u = 0; u < 4; u++) {
            float4 v = *(const float4*)(xr + u * 4);
            float* dh = &Ah[arow * ASTR + acol + u * 4];
            float* dl = &Al[arow * ASTR + acol + u * 4];
            float h0 = __uint_as_float(f2tf32(v.x));
            float h1 = __uint_as_float(f2tf32(v.y));
            float h2 = __uint_as_float(f2tf32(v.z));
            float h3 = __uint_as_float(f2tf32(v.w));
            *(float4*)dh = make_float4(h0, h1, h2, h3);
            *(float4*)dl = make_float4(v.x - h0, v.y - h1, v.z - h2, v.w - h3);
        }
        // B tile: 32 x 64 from W[k][n0+n], split
#pragma unroll
        for (int u = 0; u < 8; u++) {
            int k = bk0 + u * 4;
            float v = W[(size_t)(k0 + k) * DD + n0 + bn];
            float h = __uint_as_float(f2tf32(v));
            Bh[k * BSTR + bn] = h;
            Bl[k * BSTR + bn] = v - h;
        }
        __syncthreads();

#pragma unroll
        for (int s = 0; s < 4; s++) {      // 4 k8-steps
            const int k8 = s * 8;
            // A fragments (2 m-frags), hi+lo
            uint32_t ah[2][4], al[2][4];
#pragma unroll
            for (int mf = 0; mf < 2; mf++) {
                int r0 = wm * 32 + mf * 16;
                const float* ph = &Ah[(r0 + g) * ASTR + k8 + t];
                const float* pl = &Al[(r0 + g) * ASTR + k8 + t];
                ah[mf][0] = __float_as_uint(ph[0]);
                ah[mf][1] = __float_as_uint(ph[8 * ASTR]);
                ah[mf][2] = __float_as_uint(ph[4]);
                ah[mf][3] = __float_as_uint(ph[8 * ASTR + 4]);
                al[mf][0] = __float_as_uint(pl[0]);
                al[mf][1] = __float_as_uint(pl[8 * ASTR]);
                al[mf][2] = __float_as_uint(pl[4]);
                al[mf][3] = __float_as_uint(pl[8 * ASTR + 4]);
            }
            // B fragments (4 n-frags), hi+lo
            uint32_t bh[4][2], bl[4][2];
#pragma unroll
            for (int nf = 0; nf < 4; nf++) {
                int cbase = wn * 32 + nf * 8 + g;
                const float* ph = &Bh[(k8 + t) * BSTR + cbase];
                const float* pl = &Bl[(k8 + t) * BSTR + cbase];
                bh[nf][0] = __float_as_uint(ph[0]);
                bh[nf][1] = __float_as_uint(ph[4 * BSTR]);
                bl[nf][0] = __float_as_uint(pl[0]);
                bl[nf][1] = __float_as_uint(pl[4 * BSTR]);
            }
            // 3xTF32: hi*hi + hi*lo + lo*hi
#pragma unroll
            for (int mf = 0; mf < 2; mf++)
#pragma unroll
                for (int nf = 0; nf < 4; nf++) {
                    float* cc = c[mf][nf];
                    mma_tf32(cc[0], cc[1], cc[2], cc[3],
                             ah[mf][0], ah[mf][1], ah[mf][2], ah[mf][3],
                             bh[nf][0], bh[nf][1]);
                    mma_tf32(cc[0], cc[1], cc[2], cc[3],
                             ah[mf][0], ah[mf][1], ah[mf][2], ah[mf][3],
                             bl[nf][0], bl[nf][1]);
                    mma_tf32(cc[0], cc[1], cc[2], cc[3],
                             al[mf][0], al[mf][1], al[mf][2], al[mf][3],
                             bh[nf][0], bh[nf][1]);
                }
        }
        __syncthreads();
    }

    // Epilogue: c{0,1} -> (row g, cols 2t,2t+1); c{2,3} -> row g+8.
    float* op = g_P[which] + ((size_t)(b * HH + head) * LL + l0) * DHD;
#pragma unroll
    for (int mf = 0; mf < 2; mf++) {
        int r0 = wm * 32 + mf * 16 + g;
#pragma unroll
        for (int nf = 0; nf < 4; nf++) {
            int d0 = wn * 32 + nf * 8 + 2 * t;
            float* cc = c[mf][nf];
            *(float2*)(op + (size_t)r0 * DHD + d0) =
                make_float2(cc[0] * scale, cc[1] * scale);
            *(float2*)(op + (size_t)(r0 + 8) * DHD + d0) =
                make_float2(cc[2] * scale, cc[3] * scale);
        }
    }
}

// ---------------------------------------------------------------------------
// Flash attention (byte-identical to the passing R6 kernel).
// ---------------------------------------------------------------------------
#define QKS 136
#define VPS 68
#define PTS 132
#define ATTN_SMEM ((2 * 64 * QKS + 128 * VPS + 128 * PTS) * (int)sizeof(float))

__global__ __launch_bounds__(256, 1) void attn_kernel(
    const int* __restrict__ q_lenp, const int* __restrict__ v_lenp,
    float* __restrict__ out)
{
    const int qt  = blockIdx.x;
    const int h   = blockIdx.y;
    const int b   = blockIdx.z;
    const int tid = threadIdx.x;
    const int tx  = tid & 15;
    const int ty  = tid >> 4;
    const int l0  = qt * 128;
    const int q_len = q_lenp[b];
    const int v_len = v_lenp[b];

    float* outp = out + (size_t)b * LL * DD + h * DHD;
    const int lr = tid >> 1;
    const int lc = (tid & 1) * 32;

    if (l0 >= q_len) {
#pragma unroll
        for (int u = 0; u < 8; u++)
            *(float4*)(outp + (size_t)(l0 + lr) * DD + lc + u * 4) =
                make_float4(0.f, 0.f, 0.f, 0.f);
        return;
    }

    extern __shared__ __align__(16) float sm[];
    float* Qt = sm;
    float* Kt = sm + 64 * QKS;
    float* Vs = sm + 2 * 64 * QKS;
    float* Pt = Vs + 128 * VPS;

    const float* Qp = g_P[0] + ((size_t)(b * HH + h) * LL + l0) * DHD;
    const float* Kp = g_P[1] + (size_t)(b * HH + h) * LL * DHD;
    const float* Vp = g_P[2] + (size_t)(b * HH + h) * LL * DHD;

#pragma unroll
    for (int u = 0; u < 8; u++) {
        float4 v = *(const float4*)(Qp + (size_t)lr * DHD + lc + u * 4);
        Qt[(lc + u * 4 + 0) * QKS + lr] = v.x;
        Qt[(lc + u * 4 + 1) * QKS + lr] = v.y;
        Qt[(lc + u * 4 + 2) * QKS + lr] = v.z;
        Qt[(lc + u * 4 + 3) * QKS + lr] = v.w;
    }

    float acc[8][4];
    float m_i[8], l_i[8];
#pragma unroll
    for (int i = 0; i < 8; i++) {
        m_i[i] = -1e30f; l_i[i] = 0.f;
#pragma unroll
        for (int j = 0; j < 4; j++) acc[i][j] = 0.f;
    }

    const int nkt = (v_len + 127) >> 7;
    for (int kt = 0; kt < nkt; kt++) {
        const int k0 = kt * 128;
#pragma unroll
        for (int u = 0; u < 8; u++) {
            float4 kv = *(const float4*)(Kp + (size_t)(k0 + lr) * DHD + lc + u * 4);
            Kt[(lc + u * 4 + 0) * QKS + lr] = kv.x;
            Kt[(lc + u * 4 + 1) * QKS + lr] = kv.y;
            Kt[(lc + u * 4 + 2) * QKS + lr] = kv.z;
            Kt[(lc + u * 4 + 3) * QKS + lr] = kv.w;
            float4 vv = *(const float4*)(Vp + (size_t)(k0 + lr) * DHD + lc + u * 4);
            *(float4*)&Vs[lr * VPS + lc + u * 4] = vv;
        }
        __syncthreads();

        float s[8][8];
#pragma unroll
        for (int i = 0; i < 8; i++)
#pragma unroll
            for (int j = 0; j < 8; j++) s[i][j] = 0.f;
#pragma unroll 4
        for (int d = 0; d < 64; d++) {
            float4 a0 = *(const float4*)&Qt[d * QKS + ty * 8];
            float4 a1 = *(const float4*)&Qt[d * QKS + ty * 8 + 4];
            float4 b0 = *(const float4*)&Kt[d * QKS + tx * 8];
            float4 b1 = *(const float4*)&Kt[d * QKS + tx * 8 + 4];
            float a[8] = {a0.x, a0.y, a0.z, a0.w, a1.x, a1.y, a1.z, a1.w};
            float bb[8] = {b0.x, b0.y, b0.z, b0.w, b1.x, b1.y, b1.z, b1.w};
#pragma unroll
            for (int i = 0; i < 8; i++)
#pragma unroll
                for (int j = 0; j < 8; j++) s[i][j] += a[i] * bb[j];
        }

#pragma unroll
        for (int i = 0; i < 8; i++) {
#pragma unroll
            for (int jj = 0; jj < 8; jj++)
                if (k0 + tx * 8 + jj >= v_len) s[i][jj] = -1e30f;

            float mt = s[i][0];
#pragma unroll
            for (int jj = 1; jj < 8; jj++) mt = fmaxf(mt, s[i][jj]);
#pragma unroll
            for (int off = 1; off < 16; off <<= 1)
                mt = fmaxf(mt, __shfl_xor_sync(0xffffffffu, mt, off));
            float mn = fmaxf(m_i[i], mt);
            float alpha = __expf(m_i[i] - mn);
            float rs = 0.f;
#pragma unroll
            for (int jj = 0; jj < 8; jj++) {
                s[i][jj] = __expf(s[i][jj] - mn);
                rs += s[i][jj];
            }
#pragma unroll
            for (int off = 1; off < 16; off <<= 1)
                rs += __shfl_xor_sync(0xffffffffu, rs, off);
            l_i[i] = l_i[i] * alpha + rs;
            m_i[i] = mn;
#pragma unroll
            for (int j = 0; j < 4; j++) acc[i][j] *= alpha;
            *(float4*)&Pt[(ty * 8 + i) * PTS + tx * 8] =
                make_float4(s[i][0], s[i][1], s[i][2], s[i][3]);
            *(float4*)&Pt[(ty * 8 + i) * PTS + tx * 8 + 4] =
                make_float4(s[i][4], s[i][5], s[i][6], s[i][7]);
        }
        __syncthreads();

#pragma unroll 2
        for (int j = 0; j < 128; j++) {
            float4 b0 = *(const float4*)&Vs[j * VPS + tx * 4];
            float bb[4] = {b0.x, b0.y, b0.z, b0.w};
            float a[8];
#pragma unroll
            for (int i = 0; i < 8; i++) a[i] = Pt[(ty * 8 + i) * PTS + j];
#pragma unroll
            for (int i = 0; i < 8; i++)
#pragma unroll
                for (int jc = 0; jc < 4; jc++) acc[i][jc] += a[i] * bb[jc];
        }
        __syncthreads();
    }

#pragma unroll
    for (int i = 0; i < 8; i++) {
        int r = l0 + ty * 8 + i;
        float4 o;
        if (r < q_len) {
            float inv = 1.f / l_i[i];
            o = make_float4(acc[i][0] * inv, acc[i][1] * inv,
                            acc[i][2] * inv, acc[i][3] * inv);
        } else {
            o = make_float4(0.f, 0.f, 0.f, 0.f);
        }
        *(float4*)(outp + (size_t)r * DD + tx * 4) = o;
    }
}

// ---------------------------------------------------------------------------
extern "C" void kernel_launch(void* const* d_in, const int* in_sizes, int n_in,
                              void* d_out, int out_size)
{
    (void)in_sizes; (void)n_in; (void)out_size;
    const float* Q_seq = (const float*)d_in[0];
    const float* K_seq = (const float*)d_in[1];
    const float* V_seq = (const float*)d_in[2];
    const int*   q_len = (const int*)d_in[3];
    const int*   v_len = (const int*)d_in[4];
    const float* WQ    = (const float*)d_in[5];
    const float* WK    = (const float*)d_in[6];
    const float* WV    = (const float*)d_in[7];
    float* out = (float*)d_out;

    cudaFuncSetAttribute(proj_mma_kernel, cudaFuncAttributeMaxDynamicSharedMemorySize,
                         PROJ_SMEM);
    proj_mma_kernel<<<dim3(HH, (BB * LL) / 128, 3), 256, PROJ_SMEM>>>(
        Q_seq, K_seq, V_seq, WQ, WK, WV, q_len, v_len);

    cudaFuncSetAttribute(attn_kernel, cudaFuncAttributeMaxDynamicSharedMemorySize,
                         ATTN_SMEM);
    attn_kernel<<<dim3(LL / 128, HH, BB), 256, ATTN_SMEM>>>(q_len, v_len, out);
}